// round 1
// baseline (speedup 1.0000x reference)
#include <cuda_runtime.h>
#include <math.h>

#define BB 2
#define TT 2048
#define CC 1024
#define HH 16
#define HD 64
#define MM (BB*TT)   // 4096

// Scratch (no cudaMalloc allowed): qkv [4096, 3072], y [4096, 1024]
__device__ float g_qkv[(size_t)MM * 3 * CC];
__device__ float g_y[(size_t)MM * CC];

// ---------------------------------------------------------------------------
// SGEMM + bias: C[M,N] = A[M,K] @ B[K,N] + bias[N]
// 128x128 block tile, BK=16, 8x8 per-thread fragment, 256 threads.
// M,N,K all multiples of 128/16 here (no edge handling needed).
// ---------------------------------------------------------------------------
__global__ __launch_bounds__(256) void sgemm_bias_kernel(
    const float* __restrict__ A, const float* __restrict__ B,
    const float* __restrict__ bias, float* __restrict__ C,
    int M, int N, int K)
{
    __shared__ float As[16][128];   // [k][m] (A transposed in smem)
    __shared__ float Bs[16][128];   // [k][n]

    const int tid = threadIdx.x;
    const int tx = tid & 15;        // n-dim
    const int ty = tid >> 4;        // m-dim
    const int m0 = blockIdx.y * 128;
    const int n0 = blockIdx.x * 128;

    float acc[8][8];
    #pragma unroll
    for (int i = 0; i < 8; i++)
        #pragma unroll
        for (int j = 0; j < 8; j++) acc[i][j] = 0.f;

    for (int k0 = 0; k0 < K; k0 += 16) {
        // A tile: 128 rows x 16 cols = 512 float4 loads across 256 threads
        #pragma unroll
        for (int i = 0; i < 2; i++) {
            int lin = tid + i * 256;
            int row = lin >> 2;
            int c4  = lin & 3;
            float4 v = *(const float4*)&A[(size_t)(m0 + row) * K + k0 + c4 * 4];
            As[c4 * 4 + 0][row] = v.x;
            As[c4 * 4 + 1][row] = v.y;
            As[c4 * 4 + 2][row] = v.z;
            As[c4 * 4 + 3][row] = v.w;
        }
        // B tile: 16 rows x 128 cols
        #pragma unroll
        for (int i = 0; i < 2; i++) {
            int lin = tid + i * 256;
            int row = lin >> 5;
            int c4  = lin & 31;
            *(float4*)&Bs[row][c4 * 4] =
                *(const float4*)&B[(size_t)(k0 + row) * N + n0 + c4 * 4];
        }
        __syncthreads();

        #pragma unroll
        for (int kk = 0; kk < 16; kk++) {
            float a[8], b[8];
            *(float4*)&a[0] = *(float4*)&As[kk][ty * 8];
            *(float4*)&a[4] = *(float4*)&As[kk][ty * 8 + 4];
            *(float4*)&b[0] = *(float4*)&Bs[kk][tx * 8];
            *(float4*)&b[4] = *(float4*)&Bs[kk][tx * 8 + 4];
            #pragma unroll
            for (int i = 0; i < 8; i++)
                #pragma unroll
                for (int j = 0; j < 8; j++)
                    acc[i][j] += a[i] * b[j];
        }
        __syncthreads();
    }

    #pragma unroll
    for (int i = 0; i < 8; i++) {
        int m = m0 + ty * 8 + i;
        #pragma unroll
        for (int j4 = 0; j4 < 2; j4++) {
            int n = n0 + tx * 8 + j4 * 4;
            float4 bv = *(const float4*)&bias[n];
            float4 o;
            o.x = acc[i][j4 * 4 + 0] + bv.x;
            o.y = acc[i][j4 * 4 + 1] + bv.y;
            o.z = acc[i][j4 * 4 + 2] + bv.z;
            o.w = acc[i][j4 * 4 + 3] + bv.w;
            *(float4*)&C[(size_t)m * N + n] = o;
        }
    }
}

// ---------------------------------------------------------------------------
// Flash attention (causal), fp32. One block = one (b, h, 64-query tile).
// 256 threads = 16x16 grid, 4x4 fragment per thread over the 64x64 tiles.
// Online softmax with m/l in smem.
// ---------------------------------------------------------------------------
#define AP 68   // smem pitch (floats) — avoids bank conflicts, keeps 16B align

__global__ __launch_bounds__(256) void flash_attn_kernel()
{
    extern __shared__ float sm[];
    float* sQ = sm;              // [d][m]  64 x AP
    float* sK = sQ + 64 * AP;    // [d][n]
    float* sV = sK + 64 * AP;    // [n][d]
    float* sS = sV + 64 * AP;    // [m][n]
    float* sMx = sS + 64 * AP;   // [64] row max
    float* sL  = sMx + 64;       // [64] row sum
    float* sF  = sL + 64;        // [64] rescale factor
    float* sR  = sF + 64;        // [256] reduction scratch

    const int tid = threadIdx.x;
    const int tx = tid & 15;
    const int ty = tid >> 4;
    const int mt = blockIdx.x;   // query tile
    const int h  = blockIdx.y;
    const int b  = blockIdx.z;
    const int i0 = mt * 64;
    const int r0 = ty * 4;
    const int c0 = tx * 4;
    const float scale = 0.125f;  // 1/sqrt(64)

    if (tid < 64) { sMx[tid] = -1e30f; sL[tid] = 0.f; }

    // Load Q tile [64 rows, 64 dims] -> sQ[d][m]
    #pragma unroll
    for (int i = 0; i < 4; i++) {
        int lin = tid + i * 256;
        int row = lin >> 4;
        int d4  = lin & 15;
        float4 v = *(const float4*)&g_qkv[
            (size_t)(b * TT + i0 + row) * (3 * CC) + h * HD + d4 * 4];
        sQ[(d4 * 4 + 0) * AP + row] = v.x;
        sQ[(d4 * 4 + 1) * AP + row] = v.y;
        sQ[(d4 * 4 + 2) * AP + row] = v.z;
        sQ[(d4 * 4 + 3) * AP + row] = v.w;
    }

    float o[4][4];
    #pragma unroll
    for (int i = 0; i < 4; i++)
        #pragma unroll
        for (int j = 0; j < 4; j++) o[i][j] = 0.f;

    for (int jt = 0; jt <= mt; jt++) {
        const int j0 = jt * 64;
        __syncthreads();   // previous iteration's PV / Q-load complete

        // Load K -> sK[d][n], V -> sV[n][d]
        #pragma unroll
        for (int i = 0; i < 4; i++) {
            int lin = tid + i * 256;
            int row = lin >> 4;
            int d4  = lin & 15;
            size_t goff = (size_t)(b * TT + j0 + row) * (3 * CC) + CC + h * HD + d4 * 4;
            float4 kv = *(const float4*)&g_qkv[goff];
            sK[(d4 * 4 + 0) * AP + row] = kv.x;
            sK[(d4 * 4 + 1) * AP + row] = kv.y;
            sK[(d4 * 4 + 2) * AP + row] = kv.z;
            sK[(d4 * 4 + 3) * AP + row] = kv.w;
            float4 vv = *(const float4*)&g_qkv[goff + CC];
            *(float4*)&sV[row * AP + d4 * 4] = vv;
        }
        __syncthreads();

        // S = (Q K^T) * scale
        float s[4][4];
        #pragma unroll
        for (int i = 0; i < 4; i++)
            #pragma unroll
            for (int j = 0; j < 4; j++) s[i][j] = 0.f;
        #pragma unroll
        for (int k = 0; k < 64; k++) {
            float4 qa = *(float4*)&sQ[k * AP + r0];
            float4 kb = *(float4*)&sK[k * AP + c0];
            float a[4] = {qa.x, qa.y, qa.z, qa.w};
            float bb[4] = {kb.x, kb.y, kb.z, kb.w};
            #pragma unroll
            for (int i = 0; i < 4; i++)
                #pragma unroll
                for (int j = 0; j < 4; j++)
                    s[i][j] += a[i] * bb[j];
        }
        const bool diag = (jt == mt);
        #pragma unroll
        for (int i = 0; i < 4; i++)
            #pragma unroll
            for (int j = 0; j < 4; j++) {
                float v = s[i][j] * scale;
                if (diag && (c0 + j > r0 + i)) v = -1e30f;
                sS[(r0 + i) * AP + c0 + j] = v;
            }
        __syncthreads();

        // Row max (4 partials per row)
        {
            int row = tid >> 2, part = tid & 3;
            float mv = -1e30f;
            #pragma unroll
            for (int c = 0; c < 16; c++)
                mv = fmaxf(mv, sS[row * AP + part * 16 + c]);
            sR[row * 4 + part] = mv;
        }
        __syncthreads();
        if (tid < 64) {
            float mnew = fmaxf(fmaxf(sR[tid * 4], sR[tid * 4 + 1]),
                               fmaxf(sR[tid * 4 + 2], sR[tid * 4 + 3]));
            mnew = fmaxf(mnew, sMx[tid]);
            float f = __expf(sMx[tid] - mnew);
            sF[tid] = f;
            sMx[tid] = mnew;
            sL[tid] *= f;
        }
        __syncthreads();

        // P = exp(S - m), row-sum partials
        {
            int row = tid >> 2, part = tid & 3;
            float mrow = sMx[row];
            float sum = 0.f;
            #pragma unroll
            for (int c = 0; c < 16; c++) {
                float p = __expf(sS[row * AP + part * 16 + c] - mrow);
                sS[row * AP + part * 16 + c] = p;
                sum += p;
            }
            sR[row * 4 + part] = sum;
        }
        __syncthreads();
        if (tid < 64)
            sL[tid] += sR[tid * 4] + sR[tid * 4 + 1] + sR[tid * 4 + 2] + sR[tid * 4 + 3];

        // Rescale O, then O += P @ V
        #pragma unroll
        for (int i = 0; i < 4; i++) {
            float f = sF[r0 + i];
            #pragma unroll
            for (int j = 0; j < 4; j++) o[i][j] *= f;
        }
        #pragma unroll
        for (int n4 = 0; n4 < 16; n4++) {
            float pv[4][4];
            #pragma unroll
            for (int i = 0; i < 4; i++)
                *(float4*)pv[i] = *(float4*)&sS[(r0 + i) * AP + n4 * 4];
            #pragma unroll
            for (int u = 0; u < 4; u++) {
                int n = n4 * 4 + u;
                float4 vv = *(float4*)&sV[n * AP + c0];
                #pragma unroll
                for (int i = 0; i < 4; i++) {
                    o[i][0] += pv[i][u] * vv.x;
                    o[i][1] += pv[i][u] * vv.y;
                    o[i][2] += pv[i][u] * vv.z;
                    o[i][3] += pv[i][u] * vv.w;
                }
            }
        }
    }
    __syncthreads();  // make final sL visible

    #pragma unroll
    for (int i = 0; i < 4; i++) {
        float inv = 1.f / sL[r0 + i];
        float4 ov;
        ov.x = o[i][0] * inv;
        ov.y = o[i][1] * inv;
        ov.z = o[i][2] * inv;
        ov.w = o[i][3] * inv;
        *(float4*)&g_y[(size_t)(b * TT + i0 + r0 + i) * CC + h * HD + c0] = ov;
    }
}

// ---------------------------------------------------------------------------
extern "C" void kernel_launch(void* const* d_in, const int* in_sizes, int n_in,
                              void* d_out, int out_size)
{
    const float* x     = (const float*)d_in[0];
    const float* w_qkv = (const float*)d_in[1];
    const float* b_qkv = (const float*)d_in[2];
    const float* w_out = (const float*)d_in[3];
    const float* b_out = (const float*)d_in[4];
    float* out = (float*)d_out;

    float* qkv; cudaGetSymbolAddress((void**)&qkv, g_qkv);
    float* y;   cudaGetSymbolAddress((void**)&y,   g_y);

    // Flash-attention dynamic smem: 4 tiles of 64*AP + 3*64 + 256 floats
    const int smem_bytes = (4 * 64 * AP + 3 * 64 + 256) * (int)sizeof(float);
    cudaFuncSetAttribute(flash_attn_kernel,
                         cudaFuncAttributeMaxDynamicSharedMemorySize, smem_bytes);

    // 1) qkv = x @ w_qkv + b_qkv        [4096, 3072]
    {
        dim3 grid(3 * CC / 128, MM / 128);
        sgemm_bias_kernel<<<grid, 256>>>(x, w_qkv, b_qkv, qkv, MM, 3 * CC, CC);
    }
    // 2) flash attention -> g_y         [4096, 1024]
    {
        dim3 grid(TT / 64, HH, BB);
        flash_attn_kernel<<<grid, 256, smem_bytes>>>();
    }
    // 3) out = y @ w_out + b_out        [4096, 1024]
    {
        dim3 grid(CC / 128, MM / 128);
        sgemm_bias_kernel<<<grid, 256>>>(y, w_out, b_out, out, MM, CC, CC);
    }
}

// round 5
// speedup vs baseline: 1.4783x; 1.4783x over previous
#include <cuda_runtime.h>
#include <cuda_bf16.h>
#include <cstdint>
#include <math.h>

#define BB 2
#define TT 2048
#define CC 1024
#define HH 16
#define HD 64
#define MM (BB*TT)   // 4096

// ---------------------------------------------------------------------------
// Scratch (no cudaMalloc allowed)
// ---------------------------------------------------------------------------
__device__ float g_qkv[(size_t)MM * 3 * CC];          // [4096, 3072]
__device__ float g_y[(size_t)MM * CC];                // [4096, 1024]
__device__ __nv_bfloat16 g_xhi[(size_t)MM * CC];
__device__ __nv_bfloat16 g_xlo[(size_t)MM * CC];
__device__ __nv_bfloat16 g_yhi[(size_t)MM * CC];
__device__ __nv_bfloat16 g_ylo[(size_t)MM * CC];
__device__ __nv_bfloat16 g_wqkvT_hi[(size_t)3 * CC * CC];   // [3072, 1024] = W^T
__device__ __nv_bfloat16 g_wqkvT_lo[(size_t)3 * CC * CC];
__device__ __nv_bfloat16 g_woutT_hi[(size_t)CC * CC];       // [1024, 1024] = W^T
__device__ __nv_bfloat16 g_woutT_lo[(size_t)CC * CC];

// ---------------------------------------------------------------------------
// mma.sync / ldmatrix helpers (sm_80-baseline PTX — no arch-suffix needed)
// ---------------------------------------------------------------------------
__device__ __forceinline__ uint32_t smem_u32(const void* p) {
    uint32_t a;
    asm("{ .reg .u64 t; cvta.to.shared.u64 t, %1; cvt.u32.u64 %0, t; }"
        : "=r"(a) : "l"(p));
    return a;
}

__device__ __forceinline__ void ldsm4(uint32_t* r, uint32_t addr) {
    asm volatile("ldmatrix.sync.aligned.m8n8.x4.shared.b16 {%0,%1,%2,%3}, [%4];"
        : "=r"(r[0]), "=r"(r[1]), "=r"(r[2]), "=r"(r[3]) : "r"(addr));
}

__device__ __forceinline__ void mma_bf16(float* d, const uint32_t* a,
                                         const uint32_t* b) {
    asm volatile(
        "mma.sync.aligned.m16n8k16.row.col.f32.bf16.bf16.f32 "
        "{%0,%1,%2,%3}, {%4,%5,%6,%7}, {%8,%9}, {%0,%1,%2,%3};"
        : "+f"(d[0]), "+f"(d[1]), "+f"(d[2]), "+f"(d[3])
        : "r"(a[0]), "r"(a[1]), "r"(a[2]), "r"(a[3]), "r"(b[0]), "r"(b[1]));
}

// ---------------------------------------------------------------------------
// Prep kernels: bf16 hi/lo split (elementwise) and transpose+split for weights
// ---------------------------------------------------------------------------
__global__ __launch_bounds__(256) void split_kernel(
    const float* __restrict__ in, __nv_bfloat16* __restrict__ hi,
    __nv_bfloat16* __restrict__ lo, int n)
{
    int i = (blockIdx.x * 256 + threadIdx.x) * 4;
    if (i >= n) return;
    float4 v = *(const float4*)&in[i];
    __nv_bfloat16 h0 = __float2bfloat16(v.x), h1 = __float2bfloat16(v.y);
    __nv_bfloat16 h2 = __float2bfloat16(v.z), h3 = __float2bfloat16(v.w);
    __nv_bfloat16 l0 = __float2bfloat16(v.x - __bfloat162float(h0));
    __nv_bfloat16 l1 = __float2bfloat16(v.y - __bfloat162float(h1));
    __nv_bfloat16 l2 = __float2bfloat16(v.z - __bfloat162float(h2));
    __nv_bfloat16 l3 = __float2bfloat16(v.w - __bfloat162float(h3));
    __nv_bfloat162 hp0; hp0.x = h0; hp0.y = h1;
    __nv_bfloat162 hp1; hp1.x = h2; hp1.y = h3;
    __nv_bfloat162 lp0; lp0.x = l0; lp0.y = l1;
    __nv_bfloat162 lp1; lp1.x = l2; lp1.y = l3;
    uint2 hv, lv;
    hv.x = *(uint32_t*)&hp0; hv.y = *(uint32_t*)&hp1;
    lv.x = *(uint32_t*)&lp0; lv.y = *(uint32_t*)&lp1;
    *(uint2*)&hi[i] = hv;
    *(uint2*)&lo[i] = lv;
}

// W [K, N] row-major -> WT_hi/lo [N, K] bf16
__global__ __launch_bounds__(256) void transpose_split_kernel(
    const float* __restrict__ W, __nv_bfloat16* __restrict__ hi,
    __nv_bfloat16* __restrict__ lo, int K, int N)
{
    __shared__ float t[32][33];
    const int n0 = blockIdx.x * 32, k0 = blockIdx.y * 32;
    const int tx = threadIdx.x & 31, ty = threadIdx.x >> 5;   // 32 x 8
    #pragma unroll
    for (int i = 0; i < 32; i += 8)
        t[ty + i][tx] = W[(size_t)(k0 + ty + i) * N + n0 + tx];
    __syncthreads();
    #pragma unroll
    for (int i = 0; i < 32; i += 8) {
        float v = t[tx][ty + i];
        size_t o = (size_t)(n0 + ty + i) * K + k0 + tx;
        __nv_bfloat16 h = __float2bfloat16(v);
        hi[o] = h;
        lo[o] = __float2bfloat16(v - __bfloat162float(h));
    }
}

// ---------------------------------------------------------------------------
// mma.sync GEMM + bias: C[M,N] = (Ahi+Alo)[M,K] @ (BThi+BTlo)^T + bias
// A planes [M,K] bf16 row-major; BT planes [N,K] bf16 row-major (K contiguous
// = col-major B, exactly what mma row.col wants).
// Block 128x128, BK=32. 8 warps (2 M x 4 N), warp tile 64x32 = 4x4 m16n8k16.
// bf16x3: hi*hi + hi*lo + lo*hi, fp32 accumulate.
// ---------------------------------------------------------------------------
#define SA 40   // smem row stride in bf16 (80B: 16B-aligned, conflict-free)

__global__ __launch_bounds__(256) void mma_gemm_bias_kernel(
    const __nv_bfloat16* __restrict__ Ahi, const __nv_bfloat16* __restrict__ Alo,
    const __nv_bfloat16* __restrict__ BThi, const __nv_bfloat16* __restrict__ BTlo,
    const float* __restrict__ bias, float* __restrict__ C,
    int M, int N, int K)
{
    __shared__ __nv_bfloat16 sAhi[128 * SA];
    __shared__ __nv_bfloat16 sAlo[128 * SA];
    __shared__ __nv_bfloat16 sBhi[128 * SA];
    __shared__ __nv_bfloat16 sBlo[128 * SA];

    const int tid = threadIdx.x;
    const int wid = tid >> 5;
    const int lane = tid & 31;
    const int wm = wid >> 2;          // 0..1
    const int wn = wid & 3;           // 0..3
    const int m0 = blockIdx.y * 128;
    const int n0 = blockIdx.x * 128;

    float acc[4][4][4];
    #pragma unroll
    for (int i = 0; i < 4; i++)
        #pragma unroll
        for (int j = 0; j < 4; j++)
            #pragma unroll
            for (int r = 0; r < 4; r++) acc[i][j][r] = 0.f;

    // ldmatrix lane addressing
    // A x4 tile order: (m0-7,k0),(m8-15,k0),(m0-7,k8),(m8-15,k8)
    const int a_r = (lane & 7) + ((lane >> 3) & 1) * 8;   // row within m16
    const int a_k = ((lane >> 4) & 1) * 8;                // k offset
    // B x4 tile order: (n0-7,k0),(n0-7,k8),(n8-15,k0),(n8-15,k8)
    const int b_r = (lane & 7) + ((lane >> 4) & 1) * 8;   // row within n16
    const int b_k = ((lane >> 3) & 1) * 8;

    const uint32_t uAhi = smem_u32(sAhi), uAlo = smem_u32(sAlo);
    const uint32_t uBhi = smem_u32(sBhi), uBlo = smem_u32(sBlo);

    for (int c = 0; c < K / 32; c++) {
        const int k0 = c * 32;
        // Fill 4 planes: each 128 rows x 32 bf16 = 512 uint4, 2 per thread.
        #pragma unroll
        for (int i = 0; i < 2; i++) {
            int u = tid + i * 256;
            int row = u >> 2;
            int col8 = (u & 3) * 8;
            int soff = row * SA + col8;
            size_t ga = (size_t)(m0 + row) * K + k0 + col8;
            size_t gb = (size_t)(n0 + row) * K + k0 + col8;
            *(uint4*)&sAhi[soff] = *(const uint4*)&Ahi[ga];
            *(uint4*)&sAlo[soff] = *(const uint4*)&Alo[ga];
            *(uint4*)&sBhi[soff] = *(const uint4*)&BThi[gb];
            *(uint4*)&sBlo[soff] = *(const uint4*)&BTlo[gb];
        }
        __syncthreads();

        #pragma unroll
        for (int ks = 0; ks < 2; ks++) {
            const int kk = ks * 16;
            uint32_t aHi[4][4], aLo[4][4], bHi[2][4], bLo[2][4];
            #pragma unroll
            for (int mt = 0; mt < 4; mt++) {
                int m = wm * 64 + mt * 16 + a_r;
                uint32_t off = (uint32_t)(m * SA + kk + a_k) * 2;
                ldsm4(aHi[mt], uAhi + off);
                ldsm4(aLo[mt], uAlo + off);
            }
            #pragma unroll
            for (int np = 0; np < 2; np++) {
                int n = wn * 32 + np * 16 + b_r;
                uint32_t off = (uint32_t)(n * SA + kk + b_k) * 2;
                ldsm4(bHi[np], uBhi + off);
                ldsm4(bLo[np], uBlo + off);
            }
            #pragma unroll
            for (int mt = 0; mt < 4; mt++)
                #pragma unroll
                for (int nt = 0; nt < 4; nt++) {
                    const uint32_t* bh = &bHi[nt >> 1][(nt & 1) * 2];
                    const uint32_t* bl = &bLo[nt >> 1][(nt & 1) * 2];
                    mma_bf16(acc[mt][nt], aHi[mt], bh);
                    mma_bf16(acc[mt][nt], aHi[mt], bl);
                    mma_bf16(acc[mt][nt], aLo[mt], bh);
                }
        }
        __syncthreads();
    }

    // Epilogue: d0,d1 -> (row, col..col+1); d2,d3 -> (row+8, same cols)
    #pragma unroll
    for (int mt = 0; mt < 4; mt++) {
        #pragma unroll
        for (int nt = 0; nt < 4; nt++) {
            int row = m0 + wm * 64 + mt * 16 + (lane >> 2);
            int col = n0 + wn * 32 + nt * 8 + (lane & 3) * 2;
            float b0 = bias[col], b1 = bias[col + 1];
            float2 v0, v1;
            v0.x = acc[mt][nt][0] + b0; v0.y = acc[mt][nt][1] + b1;
            v1.x = acc[mt][nt][2] + b0; v1.y = acc[mt][nt][3] + b1;
            *(float2*)&C[(size_t)row * N + col] = v0;
            *(float2*)&C[(size_t)(row + 8) * N + col] = v1;
        }
    }
}

// ---------------------------------------------------------------------------
// Flash attention (causal), fp32 — unchanged (next round's target)
// ---------------------------------------------------------------------------
#define AP 68

__global__ __launch_bounds__(256) void flash_attn_kernel()
{
    extern __shared__ float sm[];
    float* sQ = sm;
    float* sK = sQ + 64 * AP;
    float* sV = sK + 64 * AP;
    float* sS = sV + 64 * AP;
    float* sMx = sS + 64 * AP;
    float* sL  = sMx + 64;
    float* sF  = sL + 64;
    float* sR  = sF + 64;

    const int tid = threadIdx.x;
    const int tx = tid & 15;
    const int ty = tid >> 4;
    const int mt = blockIdx.x;
    const int h  = blockIdx.y;
    const int b  = blockIdx.z;
    const int i0 = mt * 64;
    const int r0 = ty * 4;
    const int c0 = tx * 4;
    const float scale = 0.125f;

    if (tid < 64) { sMx[tid] = -1e30f; sL[tid] = 0.f; }

    #pragma unroll
    for (int i = 0; i < 4; i++) {
        int lin = tid + i * 256;
        int row = lin >> 4;
        int d4  = lin & 15;
        float4 v = *(const float4*)&g_qkv[
            (size_t)(b * TT + i0 + row) * (3 * CC) + h * HD + d4 * 4];
        sQ[(d4 * 4 + 0) * AP + row] = v.x;
        sQ[(d4 * 4 + 1) * AP + row] = v.y;
        sQ[(d4 * 4 + 2) * AP + row] = v.z;
        sQ[(d4 * 4 + 3) * AP + row] = v.w;
    }

    float o[4][4];
    #pragma unroll
    for (int i = 0; i < 4; i++)
        #pragma unroll
        for (int j = 0; j < 4; j++) o[i][j] = 0.f;

    for (int jt = 0; jt <= mt; jt++) {
        const int j0 = jt * 64;
        __syncthreads();

        #pragma unroll
        for (int i = 0; i < 4; i++) {
            int lin = tid + i * 256;
            int row = lin >> 4;
            int d4  = lin & 15;
            size_t goff = (size_t)(b * TT + j0 + row) * (3 * CC) + CC + h * HD + d4 * 4;
            float4 kv = *(const float4*)&g_qkv[goff];
            sK[(d4 * 4 + 0) * AP + row] = kv.x;
            sK[(d4 * 4 + 1) * AP + row] = kv.y;
            sK[(d4 * 4 + 2) * AP + row] = kv.z;
            sK[(d4 * 4 + 3) * AP + row] = kv.w;
            float4 vv = *(const float4*)&g_qkv[goff + CC];
            *(float4*)&sV[row * AP + d4 * 4] = vv;
        }
        __syncthreads();

        float s[4][4];
        #pragma unroll
        for (int i = 0; i < 4; i++)
            #pragma unroll
            for (int j = 0; j < 4; j++) s[i][j] = 0.f;
        #pragma unroll
        for (int k = 0; k < 64; k++) {
            float4 qa = *(float4*)&sQ[k * AP + r0];
            float4 kb = *(float4*)&sK[k * AP + c0];
            float a[4] = {qa.x, qa.y, qa.z, qa.w};
            float bb[4] = {kb.x, kb.y, kb.z, kb.w};
            #pragma unroll
            for (int i = 0; i < 4; i++)
                #pragma unroll
                for (int j = 0; j < 4; j++)
                    s[i][j] += a[i] * bb[j];
        }
        const bool diag = (jt == mt);
        #pragma unroll
        for (int i = 0; i < 4; i++)
            #pragma unroll
            for (int j = 0; j < 4; j++) {
                float v = s[i][j] * scale;
                if (diag && (c0 + j > r0 + i)) v = -1e30f;
                sS[(r0 + i) * AP + c0 + j] = v;
            }
        __syncthreads();

        {
            int row = tid >> 2, part = tid & 3;
            float mv = -1e30f;
            #pragma unroll
            for (int c = 0; c < 16; c++)
                mv = fmaxf(mv, sS[row * AP + part * 16 + c]);
            sR[row * 4 + part] = mv;
        }
        __syncthreads();
        if (tid < 64) {
            float mnew = fmaxf(fmaxf(sR[tid * 4], sR[tid * 4 + 1]),
                               fmaxf(sR[tid * 4 + 2], sR[tid * 4 + 3]));
            mnew = fmaxf(mnew, sMx[tid]);
            float f = __expf(sMx[tid] - mnew);
            sF[tid] = f;
            sMx[tid] = mnew;
            sL[tid] *= f;
        }
        __syncthreads();

        {
            int row = tid >> 2, part = tid & 3;
            float mrow = sMx[row];
            float sum = 0.f;
            #pragma unroll
            for (int c = 0; c < 16; c++) {
                float p = __expf(sS[row * AP + part * 16 + c] - mrow);
                sS[row * AP + part * 16 + c] = p;
                sum += p;
            }
            sR[row * 4 + part] = sum;
        }
        __syncthreads();
        if (tid < 64)
            sL[tid] += sR[tid * 4] + sR[tid * 4 + 1] + sR[tid * 4 + 2] + sR[tid * 4 + 3];

        #pragma unroll
        for (int i = 0; i < 4; i++) {
            float f = sF[r0 + i];
            #pragma unroll
            for (int j = 0; j < 4; j++) o[i][j] *= f;
        }
        #pragma unroll
        for (int n4 = 0; n4 < 16; n4++) {
            float pv[4][4];
            #pragma unroll
            for (int i = 0; i < 4; i++)
                *(float4*)pv[i] = *(float4*)&sS[(r0 + i) * AP + n4 * 4];
            #pragma unroll
            for (int u = 0; u < 4; u++) {
                int n = n4 * 4 + u;
                float4 vv = *(float4*)&sV[n * AP + c0];
                #pragma unroll
                for (int i = 0; i < 4; i++) {
                    o[i][0] += pv[i][u] * vv.x;
                    o[i][1] += pv[i][u] * vv.y;
                    o[i][2] += pv[i][u] * vv.z;
                    o[i][3] += pv[i][u] * vv.w;
                }
            }
        }
    }
    __syncthreads();

    #pragma unroll
    for (int i = 0; i < 4; i++) {
        float inv = 1.f / sL[r0 + i];
        float4 ov;
        ov.x = o[i][0] * inv;
        ov.y = o[i][1] * inv;
        ov.z = o[i][2] * inv;
        ov.w = o[i][3] * inv;
        *(float4*)&g_y[(size_t)(b * TT + i0 + r0 + i) * CC + h * HD + c0] = ov;
    }
}

// ---------------------------------------------------------------------------
extern "C" void kernel_launch(void* const* d_in, const int* in_sizes, int n_in,
                              void* d_out, int out_size)
{
    const float* x     = (const float*)d_in[0];
    const float* w_qkv = (const float*)d_in[1];
    const float* b_qkv = (const float*)d_in[2];
    const float* w_out = (const float*)d_in[3];
    const float* b_out = (const float*)d_in[4];
    float* out = (float*)d_out;

    float* qkv; cudaGetSymbolAddress((void**)&qkv, g_qkv);
    float* y;   cudaGetSymbolAddress((void**)&y,   g_y);
    __nv_bfloat16 *xhi, *xlo, *yhi, *ylo, *wqh, *wql, *woh, *wol;
    cudaGetSymbolAddress((void**)&xhi, g_xhi);
    cudaGetSymbolAddress((void**)&xlo, g_xlo);
    cudaGetSymbolAddress((void**)&yhi, g_yhi);
    cudaGetSymbolAddress((void**)&ylo, g_ylo);
    cudaGetSymbolAddress((void**)&wqh, g_wqkvT_hi);
    cudaGetSymbolAddress((void**)&wql, g_wqkvT_lo);
    cudaGetSymbolAddress((void**)&woh, g_woutT_hi);
    cudaGetSymbolAddress((void**)&wol, g_woutT_lo);

    const int fa_smem = (4 * 64 * AP + 3 * 64 + 256) * (int)sizeof(float);
    cudaFuncSetAttribute(flash_attn_kernel,
                         cudaFuncAttributeMaxDynamicSharedMemorySize, fa_smem);

    // 1) split x -> bf16 hi/lo
    split_kernel<<<(MM * CC / 4 + 255) / 256, 256>>>(x, xhi, xlo, MM * CC);
    // 2) transpose+split weights
    {
        dim3 g1(3 * CC / 32, CC / 32);
        transpose_split_kernel<<<g1, 256>>>(w_qkv, wqh, wql, CC, 3 * CC);
        dim3 g2(CC / 32, CC / 32);
        transpose_split_kernel<<<g2, 256>>>(w_out, woh, wol, CC, CC);
    }
    // 3) qkv = x @ w_qkv + b_qkv   [4096, 3072]
    {
        dim3 grid(3 * CC / 128, MM / 128);
        mma_gemm_bias_kernel<<<grid, 256>>>(
            xhi, xlo, wqh, wql, b_qkv, qkv, MM, 3 * CC, CC);
    }
    // 4) flash attention -> g_y
    {
        dim3 grid(TT / 64, HH, BB);
        flash_attn_kernel<<<grid, 256, fa_smem>>>();
    }
    // 5) split y -> bf16 hi/lo
    split_kernel<<<(MM * CC / 4 + 255) / 256, 256>>>(y, yhi, ylo, MM * CC);
    // 6) out = y @ w_out + b_out   [4096, 1024]
    {
        dim3 grid(CC / 128, MM / 128);
        mma_gemm_bias_kernel<<<grid, 256>>>(
            yhi, ylo, woh, wol, b_out, out, MM, CC, CC);
    }
}

// round 6
// speedup vs baseline: 2.6020x; 1.7602x over previous
#include <cuda_runtime.h>
#include <cuda_bf16.h>
#include <cstdint>
#include <math.h>

#define BB 2
#define TT 2048
#define CC 1024
#define HH 16
#define HD 64
#define MM (BB*TT)   // 4096

// ---------------------------------------------------------------------------
// Scratch (no cudaMalloc allowed)
// ---------------------------------------------------------------------------
__device__ float g_qkv[(size_t)MM * 3 * CC];          // [4096, 3072] fp32
__device__ __nv_bfloat16 g_xhi[(size_t)MM * CC];
__device__ __nv_bfloat16 g_xlo[(size_t)MM * CC];
__device__ __nv_bfloat16 g_yhi[(size_t)MM * CC];      // attention out, hi plane
__device__ __nv_bfloat16 g_ylo[(size_t)MM * CC];      // attention out, lo plane
__device__ __nv_bfloat16 g_wqkvT_hi[(size_t)3 * CC * CC];   // [3072, 1024] = W^T
__device__ __nv_bfloat16 g_wqkvT_lo[(size_t)3 * CC * CC];
__device__ __nv_bfloat16 g_woutT_hi[(size_t)CC * CC];       // [1024, 1024] = W^T
__device__ __nv_bfloat16 g_woutT_lo[(size_t)CC * CC];

// ---------------------------------------------------------------------------
// mma.sync / ldmatrix helpers (sm_80-baseline PTX)
// ---------------------------------------------------------------------------
__device__ __forceinline__ uint32_t smem_u32(const void* p) {
    uint32_t a;
    asm("{ .reg .u64 t; cvta.to.shared.u64 t, %1; cvt.u32.u64 %0, t; }"
        : "=r"(a) : "l"(p));
    return a;
}

__device__ __forceinline__ void ldsm4(uint32_t* r, uint32_t addr) {
    asm volatile("ldmatrix.sync.aligned.m8n8.x4.shared.b16 {%0,%1,%2,%3}, [%4];"
        : "=r"(r[0]), "=r"(r[1]), "=r"(r[2]), "=r"(r[3]) : "r"(addr));
}
__device__ __forceinline__ void ldsm4t(uint32_t* r, uint32_t addr) {
    asm volatile("ldmatrix.sync.aligned.m8n8.x4.trans.shared.b16 {%0,%1,%2,%3}, [%4];"
        : "=r"(r[0]), "=r"(r[1]), "=r"(r[2]), "=r"(r[3]) : "r"(addr));
}

__device__ __forceinline__ void mma_bf16(float* d, const uint32_t* a,
                                         const uint32_t* b) {
    asm volatile(
        "mma.sync.aligned.m16n8k16.row.col.f32.bf16.bf16.f32 "
        "{%0,%1,%2,%3}, {%4,%5,%6,%7}, {%8,%9}, {%0,%1,%2,%3};"
        : "+f"(d[0]), "+f"(d[1]), "+f"(d[2]), "+f"(d[3])
        : "r"(a[0]), "r"(a[1]), "r"(a[2]), "r"(a[3]), "r"(b[0]), "r"(b[1]));
}

__device__ __forceinline__ void split2(float a, float b, uint32_t& hi, uint32_t& lo) {
    __nv_bfloat162 h = __floats2bfloat162_rn(a, b);
    __nv_bfloat162 l = __floats2bfloat162_rn(a - __bfloat162float(h.x),
                                             b - __bfloat162float(h.y));
    hi = *(uint32_t*)&h;
    lo = *(uint32_t*)&l;
}

// ---------------------------------------------------------------------------
// Prep kernels (unchanged from R5)
// ---------------------------------------------------------------------------
__global__ __launch_bounds__(256) void split_kernel(
    const float* __restrict__ in, __nv_bfloat16* __restrict__ hi,
    __nv_bfloat16* __restrict__ lo, int n)
{
    int i = (blockIdx.x * 256 + threadIdx.x) * 4;
    if (i >= n) return;
    float4 v = *(const float4*)&in[i];
    uint32_t h0, l0, h1, l1;
    split2(v.x, v.y, h0, l0);
    split2(v.z, v.w, h1, l1);
    uint2 hv, lv;
    hv.x = h0; hv.y = h1;
    lv.x = l0; lv.y = l1;
    *(uint2*)&hi[i] = hv;
    *(uint2*)&lo[i] = lv;
}

// W [K, N] row-major -> WT_hi/lo [N, K] bf16
__global__ __launch_bounds__(256) void transpose_split_kernel(
    const float* __restrict__ W, __nv_bfloat16* __restrict__ hi,
    __nv_bfloat16* __restrict__ lo, int K, int N)
{
    __shared__ float t[32][33];
    const int n0 = blockIdx.x * 32, k0 = blockIdx.y * 32;
    const int tx = threadIdx.x & 31, ty = threadIdx.x >> 5;   // 32 x 8
    #pragma unroll
    for (int i = 0; i < 32; i += 8)
        t[ty + i][tx] = W[(size_t)(k0 + ty + i) * N + n0 + tx];
    __syncthreads();
    #pragma unroll
    for (int i = 0; i < 32; i += 8) {
        float v = t[tx][ty + i];
        size_t o = (size_t)(n0 + ty + i) * K + k0 + tx;
        __nv_bfloat16 h = __float2bfloat16(v);
        hi[o] = h;
        lo[o] = __float2bfloat16(v - __bfloat162float(h));
    }
}

// ---------------------------------------------------------------------------
// mma.sync GEMM + bias (unchanged from R5, passing at 256us/85us)
// ---------------------------------------------------------------------------
#define SA 40

__global__ __launch_bounds__(256) void mma_gemm_bias_kernel(
    const __nv_bfloat16* __restrict__ Ahi, const __nv_bfloat16* __restrict__ Alo,
    const __nv_bfloat16* __restrict__ BThi, const __nv_bfloat16* __restrict__ BTlo,
    const float* __restrict__ bias, float* __restrict__ C,
    int M, int N, int K)
{
    __shared__ __nv_bfloat16 sAhi[128 * SA];
    __shared__ __nv_bfloat16 sAlo[128 * SA];
    __shared__ __nv_bfloat16 sBhi[128 * SA];
    __shared__ __nv_bfloat16 sBlo[128 * SA];

    const int tid = threadIdx.x;
    const int wid = tid >> 5;
    const int lane = tid & 31;
    const int wm = wid >> 2;
    const int wn = wid & 3;
    const int m0 = blockIdx.y * 128;
    const int n0 = blockIdx.x * 128;

    float acc[4][4][4];
    #pragma unroll
    for (int i = 0; i < 4; i++)
        #pragma unroll
        for (int j = 0; j < 4; j++)
            #pragma unroll
            for (int r = 0; r < 4; r++) acc[i][j][r] = 0.f;

    const int a_r = (lane & 7) + ((lane >> 3) & 1) * 8;
    const int a_k = ((lane >> 4) & 1) * 8;
    const int b_r = (lane & 7) + ((lane >> 4) & 1) * 8;
    const int b_k = ((lane >> 3) & 1) * 8;

    const uint32_t uAhi = smem_u32(sAhi), uAlo = smem_u32(sAlo);
    const uint32_t uBhi = smem_u32(sBhi), uBlo = smem_u32(sBlo);

    for (int c = 0; c < K / 32; c++) {
        const int k0 = c * 32;
        #pragma unroll
        for (int i = 0; i < 2; i++) {
            int u = tid + i * 256;
            int row = u >> 2;
            int col8 = (u & 3) * 8;
            int soff = row * SA + col8;
            size_t ga = (size_t)(m0 + row) * K + k0 + col8;
            size_t gb = (size_t)(n0 + row) * K + k0 + col8;
            *(uint4*)&sAhi[soff] = *(const uint4*)&Ahi[ga];
            *(uint4*)&sAlo[soff] = *(const uint4*)&Alo[ga];
            *(uint4*)&sBhi[soff] = *(const uint4*)&BThi[gb];
            *(uint4*)&sBlo[soff] = *(const uint4*)&BTlo[gb];
        }
        __syncthreads();

        #pragma unroll
        for (int ks = 0; ks < 2; ks++) {
            const int kk = ks * 16;
            uint32_t aHi[4][4], aLo[4][4], bHi[2][4], bLo[2][4];
            #pragma unroll
            for (int mt = 0; mt < 4; mt++) {
                int m = wm * 64 + mt * 16 + a_r;
                uint32_t off = (uint32_t)(m * SA + kk + a_k) * 2;
                ldsm4(aHi[mt], uAhi + off);
                ldsm4(aLo[mt], uAlo + off);
            }
            #pragma unroll
            for (int np = 0; np < 2; np++) {
                int n = wn * 32 + np * 16 + b_r;
                uint32_t off = (uint32_t)(n * SA + kk + b_k) * 2;
                ldsm4(bHi[np], uBhi + off);
                ldsm4(bLo[np], uBlo + off);
            }
            #pragma unroll
            for (int mt = 0; mt < 4; mt++)
                #pragma unroll
                for (int nt = 0; nt < 4; nt++) {
                    const uint32_t* bh = &bHi[nt >> 1][(nt & 1) * 2];
                    const uint32_t* bl = &bLo[nt >> 1][(nt & 1) * 2];
                    mma_bf16(acc[mt][nt], aHi[mt], bh);
                    mma_bf16(acc[mt][nt], aHi[mt], bl);
                    mma_bf16(acc[mt][nt], aLo[mt], bh);
                }
        }
        __syncthreads();
    }

    #pragma unroll
    for (int mt = 0; mt < 4; mt++) {
        #pragma unroll
        for (int nt = 0; nt < 4; nt++) {
            int row = m0 + wm * 64 + mt * 16 + (lane >> 2);
            int col = n0 + wn * 32 + nt * 8 + (lane & 3) * 2;
            float b0 = bias[col], b1 = bias[col + 1];
            float2 v0, v1;
            v0.x = acc[mt][nt][0] + b0; v0.y = acc[mt][nt][1] + b1;
            v1.x = acc[mt][nt][2] + b0; v1.y = acc[mt][nt][3] + b1;
            *(float2*)&C[(size_t)row * N + col] = v0;
            *(float2*)&C[(size_t)(row + 8) * N + col] = v1;
        }
    }
}

// ---------------------------------------------------------------------------
// Flash attention via mma.sync (causal), bf16x3 split everywhere.
// Block = 256 threads (8 warps), q-tile = 128 rows (warp w owns rows w*16..+15).
// Key tiles of 64. Writes y directly as bf16 hi/lo planes.
// ---------------------------------------------------------------------------
#define FP 72        // smem pitch in bf16 (144B = +4 banks/row: conflict-free ldsm)
#define SQH 0
#define SQL (SQH + 128 * FP * 2)
#define SKH (SQL + 128 * FP * 2)
#define SKL (SKH + 64 * FP * 2)
#define SVH (SKL + 64 * FP * 2)
#define SVL (SVH + 64 * FP * 2)
#define FA_SMEM (SVL + 64 * FP * 2)   // 73728 B

__global__ __launch_bounds__(256) void flash_attn_mma_kernel()
{
    extern __shared__ char smem[];
    const uint32_t sb = smem_u32(smem);

    const int tid = threadIdx.x;
    const int lane = tid & 31;
    const int w = tid >> 5;                       // warp 0..7
    const int mt = (TT / 128 - 1) - blockIdx.x;   // heavy tiles first
    const int h = blockIdx.y;
    const int b = blockIdx.z;
    const int i0 = mt * 128;
    const int g = lane >> 2;                      // row group within m16
    const int tig = lane & 3;

    // ldmatrix lane addressing (same conventions as GEMM kernel)
    const int a_r = (lane & 7) + ((lane >> 3) & 1) * 8;
    const int a_k = ((lane >> 4) & 1) * 8;
    const int b_r = (lane & 7) + ((lane >> 4) & 1) * 8;
    const int b_k = ((lane >> 3) & 1) * 8;
    // trans ldsm (V): tiles (k0,n0),(k8,n0),(k0,n8),(k8,n8)
    const int v_r = (lane & 7) + ((lane >> 3) & 1) * 8;   // k within 16
    const int v_n = ((lane >> 4) & 1) * 8;                // n offset

    // Load Q tile: 128 rows x 64 dims fp32 -> hi/lo bf16 smem
    #pragma unroll
    for (int i = 0; i < 8; i++) {
        int lin = tid + i * 256;
        int row = lin >> 4;
        int d4 = (lin & 15) * 4;
        float4 v = *(const float4*)&g_qkv[
            (size_t)(b * TT + i0 + row) * (3 * CC) + h * HD + d4];
        uint32_t h0, l0, h1, l1;
        split2(v.x, v.y, h0, l0);
        split2(v.z, v.w, h1, l1);
        uint2 hv; hv.x = h0; hv.y = h1;
        uint2 lv; lv.x = l0; lv.y = l1;
        *(uint2*)(smem + SQH + (row * FP + d4) * 2) = hv;
        *(uint2*)(smem + SQL + (row * FP + d4) * 2) = lv;
    }

    float O[8][4];
    #pragma unroll
    for (int j = 0; j < 8; j++)
        #pragma unroll
        for (int e = 0; e < 4; e++) O[j][e] = 0.f;
    float m0 = -1e30f, m1 = -1e30f, l0 = 0.f, l1 = 0.f;

    const int qrow0 = i0 + w * 16 + g;
    const int qrow1 = qrow0 + 8;
    const int jt_max = 2 * mt + 1;

    for (int jt = 0; jt <= jt_max; jt++) {
        const int j0 = jt * 64;
        __syncthreads();
        // Load K,V tiles: 64 x 64 fp32 each -> hi/lo bf16 smem
        #pragma unroll
        for (int i = 0; i < 4; i++) {
            int lin = tid + i * 256;
            int row = lin >> 4;
            int d4 = (lin & 15) * 4;
            size_t go = (size_t)(b * TT + j0 + row) * (3 * CC) + CC + h * HD + d4;
            float4 kv = *(const float4*)&g_qkv[go];
            float4 vv = *(const float4*)&g_qkv[go + CC];
            uint32_t h0r, l0r, h1r, l1r;
            split2(kv.x, kv.y, h0r, l0r);
            split2(kv.z, kv.w, h1r, l1r);
            uint2 hv; hv.x = h0r; hv.y = h1r;
            uint2 lv; lv.x = l0r; lv.y = l1r;
            *(uint2*)(smem + SKH + (row * FP + d4) * 2) = hv;
            *(uint2*)(smem + SKL + (row * FP + d4) * 2) = lv;
            split2(vv.x, vv.y, h0r, l0r);
            split2(vv.z, vv.w, h1r, l1r);
            hv.x = h0r; hv.y = h1r;
            lv.x = l0r; lv.y = l1r;
            *(uint2*)(smem + SVH + (row * FP + d4) * 2) = hv;
            *(uint2*)(smem + SVL + (row * FP + d4) * 2) = lv;
        }
        __syncthreads();

        // ---- S = Q K^T (bf16x3) ----
        float s[8][4];
        #pragma unroll
        for (int j = 0; j < 8; j++)
            #pragma unroll
            for (int e = 0; e < 4; e++) s[j][e] = 0.f;

        #pragma unroll
        for (int ks = 0; ks < 4; ks++) {
            uint32_t aH[4], aL[4];
            uint32_t qoff = (uint32_t)((w * 16 + a_r) * FP + ks * 16 + a_k) * 2;
            ldsm4(aH, sb + SQH + qoff);
            ldsm4(aL, sb + SQL + qoff);
            #pragma unroll
            for (int nf = 0; nf < 4; nf++) {
                uint32_t bH[4], bL[4];
                uint32_t koff = (uint32_t)((nf * 16 + b_r) * FP + ks * 16 + b_k) * 2;
                ldsm4(bH, sb + SKH + koff);
                ldsm4(bL, sb + SKL + koff);
                #pragma unroll
                for (int jj = 0; jj < 2; jj++) {
                    float* acc = s[nf * 2 + jj];
                    mma_bf16(acc, aH, &bH[jj * 2]);
                    mma_bf16(acc, aH, &bL[jj * 2]);
                    mma_bf16(acc, aL, &bH[jj * 2]);
                }
            }
        }

        // ---- scale + causal mask ----
        const bool need_mask = (j0 + 63 > qrow0);   // warp-row overlap with diag
        #pragma unroll
        for (int j = 0; j < 8; j++) {
            int colb = j0 + j * 8 + tig * 2;
            #pragma unroll
            for (int e = 0; e < 4; e++) {
                float v = s[j][e] * 0.125f;
                if (need_mask) {
                    int col = colb + (e & 1);
                    int row = (e < 2) ? qrow0 : qrow1;
                    if (col > row) v = -1e30f;
                }
                s[j][e] = v;
            }
        }

        // ---- online softmax ----
        float mx0 = -1e30f, mx1 = -1e30f;
        #pragma unroll
        for (int j = 0; j < 8; j++) {
            mx0 = fmaxf(mx0, fmaxf(s[j][0], s[j][1]));
            mx1 = fmaxf(mx1, fmaxf(s[j][2], s[j][3]));
        }
        mx0 = fmaxf(mx0, __shfl_xor_sync(0xffffffffu, mx0, 1));
        mx0 = fmaxf(mx0, __shfl_xor_sync(0xffffffffu, mx0, 2));
        mx1 = fmaxf(mx1, __shfl_xor_sync(0xffffffffu, mx1, 1));
        mx1 = fmaxf(mx1, __shfl_xor_sync(0xffffffffu, mx1, 2));
        float mn0 = fmaxf(m0, mx0), mn1 = fmaxf(m1, mx1);
        float f0 = __expf(m0 - mn0), f1 = __expf(m1 - mn1);
        m0 = mn0; m1 = mn1;

        float sum0 = 0.f, sum1 = 0.f;
        #pragma unroll
        for (int j = 0; j < 8; j++) {
            s[j][0] = __expf(s[j][0] - mn0);
            s[j][1] = __expf(s[j][1] - mn0);
            s[j][2] = __expf(s[j][2] - mn1);
            s[j][3] = __expf(s[j][3] - mn1);
            sum0 += s[j][0] + s[j][1];
            sum1 += s[j][2] + s[j][3];
        }
        sum0 += __shfl_xor_sync(0xffffffffu, sum0, 1);
        sum0 += __shfl_xor_sync(0xffffffffu, sum0, 2);
        sum1 += __shfl_xor_sync(0xffffffffu, sum1, 1);
        sum1 += __shfl_xor_sync(0xffffffffu, sum1, 2);
        l0 = l0 * f0 + sum0;
        l1 = l1 * f1 + sum1;

        #pragma unroll
        for (int j = 0; j < 8; j++) {
            O[j][0] *= f0; O[j][1] *= f0;
            O[j][2] *= f1; O[j][3] *= f1;
        }

        // ---- O += P V (bf16x3, P from register C-frags) ----
        #pragma unroll
        for (int ks2 = 0; ks2 < 4; ks2++) {
            uint32_t aPh[4], aPl[4];
            const float* p0 = s[ks2 * 2];
            const float* p1 = s[ks2 * 2 + 1];
            split2(p0[0], p0[1], aPh[0], aPl[0]);
            split2(p0[2], p0[3], aPh[1], aPl[1]);
            split2(p1[0], p1[1], aPh[2], aPl[2]);
            split2(p1[2], p1[3], aPh[3], aPl[3]);
            #pragma unroll
            for (int nf = 0; nf < 4; nf++) {
                uint32_t vH[4], vL[4];
                uint32_t voff = (uint32_t)((ks2 * 16 + v_r) * FP + nf * 16 + v_n) * 2;
                ldsm4t(vH, sb + SVH + voff);
                ldsm4t(vL, sb + SVL + voff);
                #pragma unroll
                for (int jj = 0; jj < 2; jj++) {
                    float* acc = O[nf * 2 + jj];
                    mma_bf16(acc, aPh, &vH[jj * 2]);
                    mma_bf16(acc, aPh, &vL[jj * 2]);
                    mma_bf16(acc, aPl, &vH[jj * 2]);
                }
            }
        }
    }

    // ---- epilogue: y = O / l, write bf16 hi/lo planes ----
    const float inv0 = 1.f / l0, inv1 = 1.f / l1;
    #pragma unroll
    for (int j = 0; j < 8; j++) {
        int col = h * HD + j * 8 + tig * 2;
        size_t o0 = (size_t)(b * TT + qrow0 - i0 + i0) * CC + col;   // row qrow0
        size_t o1 = o0 + 8 * CC;                                     // row qrow1
        uint32_t hv, lv;
        split2(O[j][0] * inv0, O[j][1] * inv0, hv, lv);
        *(uint32_t*)&g_yhi[o0] = hv;
        *(uint32_t*)&g_ylo[o0] = lv;
        split2(O[j][2] * inv1, O[j][3] * inv1, hv, lv);
        *(uint32_t*)&g_yhi[o1] = hv;
        *(uint32_t*)&g_ylo[o1] = lv;
    }
}

// ---------------------------------------------------------------------------
extern "C" void kernel_launch(void* const* d_in, const int* in_sizes, int n_in,
                              void* d_out, int out_size)
{
    const float* x     = (const float*)d_in[0];
    const float* w_qkv = (const float*)d_in[1];
    const float* b_qkv = (const float*)d_in[2];
    const float* w_out = (const float*)d_in[3];
    const float* b_out = (const float*)d_in[4];
    float* out = (float*)d_out;

    float* qkv; cudaGetSymbolAddress((void**)&qkv, g_qkv);
    __nv_bfloat16 *xhi, *xlo, *yhi, *ylo, *wqh, *wql, *woh, *wol;
    cudaGetSymbolAddress((void**)&xhi, g_xhi);
    cudaGetSymbolAddress((void**)&xlo, g_xlo);
    cudaGetSymbolAddress((void**)&yhi, g_yhi);
    cudaGetSymbolAddress((void**)&ylo, g_ylo);
    cudaGetSymbolAddress((void**)&wqh, g_wqkvT_hi);
    cudaGetSymbolAddress((void**)&wql, g_wqkvT_lo);
    cudaGetSymbolAddress((void**)&woh, g_woutT_hi);
    cudaGetSymbolAddress((void**)&wol, g_woutT_lo);

    cudaFuncSetAttribute(flash_attn_mma_kernel,
                         cudaFuncAttributeMaxDynamicSharedMemorySize, FA_SMEM);

    // 1) split x -> bf16 hi/lo
    split_kernel<<<(MM * CC / 4 + 255) / 256, 256>>>(x, xhi, xlo, MM * CC);
    // 2) transpose+split weights
    {
        dim3 g1(3 * CC / 32, CC / 32);
        transpose_split_kernel<<<g1, 256>>>(w_qkv, wqh, wql, CC, 3 * CC);
        dim3 g2(CC / 32, CC / 32);
        transpose_split_kernel<<<g2, 256>>>(w_out, woh, wol, CC, CC);
    }
    // 3) qkv = x @ w_qkv + b_qkv   [4096, 3072]
    {
        dim3 grid(3 * CC / 128, MM / 128);
        mma_gemm_bias_kernel<<<grid, 256>>>(
            xhi, xlo, wqh, wql, b_qkv, qkv, MM, 3 * CC, CC);
    }
    // 4) flash attention (mma.sync) -> g_yhi/g_ylo directly
    {
        dim3 grid(TT / 128, HH, BB);
        flash_attn_mma_kernel<<<grid, 256, FA_SMEM>>>();
    }
    // 5) out = y @ w_out + b_out   [4096, 1024]
    {
        dim3 grid(CC / 128, MM / 128);
        mma_gemm_bias_kernel<<<grid, 256>>>(
            yhi, ylo, woh, wol, b_out, out, MM, CC, CC);
    }
}

// round 15
// speedup vs baseline: 2.6415x; 1.0152x over previous
#include <cuda_runtime.h>
#include <cuda_bf16.h>
#include <cstdint>
#include <math.h>

#define BB 2
#define TT 2048
#define CC 1024
#define HH 16
#define HD 64
#define MM (BB*TT)   // 4096

// ---------------------------------------------------------------------------
// Scratch (no cudaMalloc allowed)
// ---------------------------------------------------------------------------
__device__ float g_qkv[(size_t)MM * 3 * CC];          // [4096, 3072] fp32
__device__ __nv_bfloat16 g_xhi[(size_t)MM * CC];
__device__ __nv_bfloat16 g_xlo[(size_t)MM * CC];
__device__ __nv_bfloat16 g_yhi[(size_t)MM * CC];      // attention out, hi plane
__device__ __nv_bfloat16 g_ylo[(size_t)MM * CC];      // attention out, lo plane
__device__ __nv_bfloat16 g_wqkvT_hi[(size_t)3 * CC * CC];   // [3072, 1024] = W^T
__device__ __nv_bfloat16 g_wqkvT_lo[(size_t)3 * CC * CC];
__device__ __nv_bfloat16 g_woutT_hi[(size_t)CC * CC];       // [1024, 1024] = W^T
__device__ __nv_bfloat16 g_woutT_lo[(size_t)CC * CC];

// ---------------------------------------------------------------------------
// mma.sync / ldmatrix / cp.async helpers (sm_80-baseline PTX)
// ---------------------------------------------------------------------------
__device__ __forceinline__ uint32_t smem_u32(const void* p) {
    uint32_t a;
    asm("{ .reg .u64 t; cvta.to.shared.u64 t, %1; cvt.u32.u64 %0, t; }"
        : "=r"(a) : "l"(p));
    return a;
}

__device__ __forceinline__ void ldsm4(uint32_t* r, uint32_t addr) {
    asm volatile("ldmatrix.sync.aligned.m8n8.x4.shared.b16 {%0,%1,%2,%3}, [%4];"
        : "=r"(r[0]), "=r"(r[1]), "=r"(r[2]), "=r"(r[3]) : "r"(addr));
}
__device__ __forceinline__ void ldsm4t(uint32_t* r, uint32_t addr) {
    asm volatile("ldmatrix.sync.aligned.m8n8.x4.trans.shared.b16 {%0,%1,%2,%3}, [%4];"
        : "=r"(r[0]), "=r"(r[1]), "=r"(r[2]), "=r"(r[3]) : "r"(addr));
}

__device__ __forceinline__ void mma_bf16(float* d, const uint32_t* a,
                                         const uint32_t* b) {
    asm volatile(
        "mma.sync.aligned.m16n8k16.row.col.f32.bf16.bf16.f32 "
        "{%0,%1,%2,%3}, {%4,%5,%6,%7}, {%8,%9}, {%0,%1,%2,%3};"
        : "+f"(d[0]), "+f"(d[1]), "+f"(d[2]), "+f"(d[3])
        : "r"(a[0]), "r"(a[1]), "r"(a[2]), "r"(a[3]), "r"(b[0]), "r"(b[1]));
}

__device__ __forceinline__ void cpa16(uint32_t dst, const void* src) {
    asm volatile("cp.async.cg.shared.global [%0], [%1], 16;"
                 :: "r"(dst), "l"(src));
}
#define CP_COMMIT() asm volatile("cp.async.commit_group;" ::: "memory")
#define CP_WAIT0()  asm volatile("cp.async.wait_group 0;" ::: "memory")

__device__ __forceinline__ void split2(float a, float b, uint32_t& hi, uint32_t& lo) {
    __nv_bfloat162 h = __floats2bfloat162_rn(a, b);
    __nv_bfloat162 l = __floats2bfloat162_rn(a - __bfloat162float(h.x),
                                             b - __bfloat162float(h.y));
    hi = *(uint32_t*)&h;
    lo = *(uint32_t*)&l;
}

// ---------------------------------------------------------------------------
// Prep kernels
// ---------------------------------------------------------------------------
__global__ __launch_bounds__(256) void split_kernel(
    const float* __restrict__ in, __nv_bfloat16* __restrict__ hi,
    __nv_bfloat16* __restrict__ lo, int n)
{
    int i = (blockIdx.x * 256 + threadIdx.x) * 4;
    if (i >= n) return;
    float4 v = *(const float4*)&in[i];
    uint32_t h0, l0, h1, l1;
    split2(v.x, v.y, h0, l0);
    split2(v.z, v.w, h1, l1);
    uint2 hv, lv;
    hv.x = h0; hv.y = h1;
    lv.x = l0; lv.y = l1;
    *(uint2*)&hi[i] = hv;
    *(uint2*)&lo[i] = lv;
}

// W [K, N] row-major -> WT_hi/lo [N, K] bf16
__global__ __launch_bounds__(256) void transpose_split_kernel(
    const float* __restrict__ W, __nv_bfloat16* __restrict__ hi,
    __nv_bfloat16* __restrict__ lo, int K, int N)
{
    __shared__ float t[32][33];
    const int n0 = blockIdx.x * 32, k0 = blockIdx.y * 32;
    const int tx = threadIdx.x & 31, ty = threadIdx.x >> 5;   // 32 x 8
    #pragma unroll
    for (int i = 0; i < 32; i += 8)
        t[ty + i][tx] = W[(size_t)(k0 + ty + i) * N + n0 + tx];
    __syncthreads();
    #pragma unroll
    for (int i = 0; i < 32; i += 8) {
        float v = t[tx][ty + i];
        size_t o = (size_t)(n0 + ty + i) * K + k0 + tx;
        __nv_bfloat16 h = __float2bfloat16(v);
        hi[o] = h;
        lo[o] = __float2bfloat16(v - __bfloat162float(h));
    }
}

// ---------------------------------------------------------------------------
// mma.sync GEMM + bias, cp.async 2-stage double-buffered.
// C[M,N] = (Ahi+Alo)[M,K] @ (BThi+BTlo)^T + bias
// Block 128x128, BK=32, 8 warps (2Mx4N), warp tile 64x32. bf16x3 split.
// ---------------------------------------------------------------------------
#define SA 40                       // smem row stride (bf16)
#define PL (128 * SA * 2)           // bytes per plane per stage = 10240
#define GEMM_SMEM_DYN (8 * PL)      // 2 stages x 4 planes = 81920 B

__device__ __forceinline__ void gemm_issue_load(
    uint32_t sbase, int stg, int k0, int tid, int m0, int n0, int K,
    const __nv_bfloat16* Ahi, const __nv_bfloat16* Alo,
    const __nv_bfloat16* BThi, const __nv_bfloat16* BTlo)
{
    uint32_t base = sbase + (uint32_t)stg * 4 * PL;
    #pragma unroll
    for (int i = 0; i < 2; i++) {
        int u = tid + i * 256;
        int row = u >> 2;
        int col8 = (u & 3) * 8;
        uint32_t soff = (uint32_t)(row * SA + col8) * 2;
        size_t ga = (size_t)(m0 + row) * K + k0 + col8;
        size_t gb = (size_t)(n0 + row) * K + k0 + col8;
        cpa16(base + soff, &Ahi[ga]);
        cpa16(base + PL + soff, &Alo[ga]);
        cpa16(base + 2 * PL + soff, &BThi[gb]);
        cpa16(base + 3 * PL + soff, &BTlo[gb]);
    }
}

__global__ __launch_bounds__(256) void mma_gemm_bias_kernel(
    const __nv_bfloat16* __restrict__ Ahi, const __nv_bfloat16* __restrict__ Alo,
    const __nv_bfloat16* __restrict__ BThi, const __nv_bfloat16* __restrict__ BTlo,
    const float* __restrict__ bias, float* __restrict__ C,
    int M, int N, int K)
{
    extern __shared__ char gsm[];
    const uint32_t sb = smem_u32(gsm);

    const int tid = threadIdx.x;
    const int wid = tid >> 5;
    const int lane = tid & 31;
    const int wm = wid >> 2;
    const int wn = wid & 3;
    const int m0 = blockIdx.y * 128;
    const int n0 = blockIdx.x * 128;

    float acc[4][4][4];
    #pragma unroll
    for (int i = 0; i < 4; i++)
        #pragma unroll
        for (int j = 0; j < 4; j++)
            #pragma unroll
            for (int r = 0; r < 4; r++) acc[i][j][r] = 0.f;

    const int a_r = (lane & 7) + ((lane >> 3) & 1) * 8;
    const int a_k = ((lane >> 4) & 1) * 8;
    const int b_r = (lane & 7) + ((lane >> 4) & 1) * 8;
    const int b_k = ((lane >> 3) & 1) * 8;

    const int nc = K / 32;
    gemm_issue_load(sb, 0, 0, tid, m0, n0, K, Ahi, Alo, BThi, BTlo);
    CP_COMMIT();

    for (int c = 0; c < nc; c++) {
        CP_WAIT0();
        __syncthreads();
        if (c + 1 < nc) {
            gemm_issue_load(sb, (c + 1) & 1, (c + 1) * 32, tid, m0, n0, K,
                            Ahi, Alo, BThi, BTlo);
            CP_COMMIT();
        }
        const uint32_t st = sb + (uint32_t)(c & 1) * 4 * PL;
        const uint32_t uAhi = st, uAlo = st + PL;
        const uint32_t uBhi = st + 2 * PL, uBlo = st + 3 * PL;

        #pragma unroll
        for (int ks = 0; ks < 2; ks++) {
            const int kk = ks * 16;
            uint32_t aHi[4][4], aLo[4][4], bHi[2][4], bLo[2][4];
            #pragma unroll
            for (int mt = 0; mt < 4; mt++) {
                int m = wm * 64 + mt * 16 + a_r;
                uint32_t off = (uint32_t)(m * SA + kk + a_k) * 2;
                ldsm4(aHi[mt], uAhi + off);
                ldsm4(aLo[mt], uAlo + off);
            }
            #pragma unroll
            for (int np = 0; np < 2; np++) {
                int n = wn * 32 + np * 16 + b_r;
                uint32_t off = (uint32_t)(n * SA + kk + b_k) * 2;
                ldsm4(bHi[np], uBhi + off);
                ldsm4(bLo[np], uBlo + off);
            }
            #pragma unroll
            for (int mt = 0; mt < 4; mt++)
                #pragma unroll
                for (int nt = 0; nt < 4; nt++) {
                    const uint32_t* bh = &bHi[nt >> 1][(nt & 1) * 2];
                    const uint32_t* bl = &bLo[nt >> 1][(nt & 1) * 2];
                    mma_bf16(acc[mt][nt], aHi[mt], bh);
                    mma_bf16(acc[mt][nt], aHi[mt], bl);
                    mma_bf16(acc[mt][nt], aLo[mt], bh);
                }
        }
    }

    #pragma unroll
    for (int mt = 0; mt < 4; mt++) {
        #pragma unroll
        for (int nt = 0; nt < 4; nt++) {
            int row = m0 + wm * 64 + mt * 16 + (lane >> 2);
            int col = n0 + wn * 32 + nt * 8 + (lane & 3) * 2;
            float b0 = bias[col], b1 = bias[col + 1];
            float2 v0, v1;
            v0.x = acc[mt][nt][0] + b0; v0.y = acc[mt][nt][1] + b1;
            v1.x = acc[mt][nt][2] + b0; v1.y = acc[mt][nt][3] + b1;
            *(float2*)&C[(size_t)row * N + col] = v0;
            *(float2*)&C[(size_t)(row + 8) * N + col] = v1;
        }
    }
}

// ---------------------------------------------------------------------------
// Flash attention via mma.sync (causal), bf16x3 split — unchanged from R6
// ---------------------------------------------------------------------------
#define FP 72
#define SQH 0
#define SQL (SQH + 128 * FP * 2)
#define SKH (SQL + 128 * FP * 2)
#define SKL (SKH + 64 * FP * 2)
#define SVH (SKL + 64 * FP * 2)
#define SVL (SVH + 64 * FP * 2)
#define FA_SMEM (SVL + 64 * FP * 2)   // 73728 B

__global__ __launch_bounds__(256) void flash_attn_mma_kernel()
{
    extern __shared__ char smem[];
    const uint32_t sb = smem_u32(smem);

    const int tid = threadIdx.x;
    const int lane = tid & 31;
    const int w = tid >> 5;
    const int mt = (TT / 128 - 1) - blockIdx.x;
    const int h = blockIdx.y;
    const int b = blockIdx.z;
    const int i0 = mt * 128;
    const int g = lane >> 2;
    const int tig = lane & 3;

    const int a_r = (lane & 7) + ((lane >> 3) & 1) * 8;
    const int a_k = ((lane >> 4) & 1) * 8;
    const int b_r = (lane & 7) + ((lane >> 4) & 1) * 8;
    const int b_k = ((lane >> 3) & 1) * 8;
    const int v_r = (lane & 7) + ((lane >> 3) & 1) * 8;
    const int v_n = ((lane >> 4) & 1) * 8;

    #pragma unroll
    for (int i = 0; i < 8; i++) {
        int lin = tid + i * 256;
        int row = lin >> 4;
        int d4 = (lin & 15) * 4;
        float4 v = *(const float4*)&g_qkv[
            (size_t)(b * TT + i0 + row) * (3 * CC) + h * HD + d4];
        uint32_t h0, l0, h1, l1;
        split2(v.x, v.y, h0, l0);
        split2(v.z, v.w, h1, l1);
        uint2 hv; hv.x = h0; hv.y = h1;
        uint2 lv; lv.x = l0; lv.y = l1;
        *(uint2*)(smem + SQH + (row * FP + d4) * 2) = hv;
        *(uint2*)(smem + SQL + (row * FP + d4) * 2) = lv;
    }

    float O[8][4];
    #pragma unroll
    for (int j = 0; j < 8; j++)
        #pragma unroll
        for (int e = 0; e < 4; e++) O[j][e] = 0.f;
    float m0 = -1e30f, m1 = -1e30f, l0 = 0.f, l1 = 0.f;

    const int qrow0 = i0 + w * 16 + g;
    const int qrow1 = qrow0 + 8;
    const int jt_max = 2 * mt + 1;

    for (int jt = 0; jt <= jt_max; jt++) {
        const int j0 = jt * 64;
        __syncthreads();
        #pragma unroll
        for (int i = 0; i < 4; i++) {
            int lin = tid + i * 256;
            int row = lin >> 4;
            int d4 = (lin & 15) * 4;
            size_t go = (size_t)(b * TT + j0 + row) * (3 * CC) + CC + h * HD + d4;
            float4 kv = *(const float4*)&g_qkv[go];
            float4 vv = *(const float4*)&g_qkv[go + CC];
            uint32_t h0r, l0r, h1r, l1r;
            split2(kv.x, kv.y, h0r, l0r);
            split2(kv.z, kv.w, h1r, l1r);
            uint2 hv; hv.x = h0r; hv.y = h1r;
            uint2 lv; lv.x = l0r; lv.y = l1r;
            *(uint2*)(smem + SKH + (row * FP + d4) * 2) = hv;
            *(uint2*)(smem + SKL + (row * FP + d4) * 2) = lv;
            split2(vv.x, vv.y, h0r, l0r);
            split2(vv.z, vv.w, h1r, l1r);
            hv.x = h0r; hv.y = h1r;
            lv.x = l0r; lv.y = l1r;
            *(uint2*)(smem + SVH + (row * FP + d4) * 2) = hv;
            *(uint2*)(smem + SVL + (row * FP + d4) * 2) = lv;
        }
        __syncthreads();

        float s[8][4];
        #pragma unroll
        for (int j = 0; j < 8; j++)
            #pragma unroll
            for (int e = 0; e < 4; e++) s[j][e] = 0.f;

        #pragma unroll
        for (int ks = 0; ks < 4; ks++) {
            uint32_t aH[4], aL[4];
            uint32_t qoff = (uint32_t)((w * 16 + a_r) * FP + ks * 16 + a_k) * 2;
            ldsm4(aH, sb + SQH + qoff);
            ldsm4(aL, sb + SQL + qoff);
            #pragma unroll
            for (int nf = 0; nf < 4; nf++) {
                uint32_t bH[4], bL[4];
                uint32_t koff = (uint32_t)((nf * 16 + b_r) * FP + ks * 16 + b_k) * 2;
                ldsm4(bH, sb + SKH + koff);
                ldsm4(bL, sb + SKL + koff);
                #pragma unroll
                for (int jj = 0; jj < 2; jj++) {
                    float* acc = s[nf * 2 + jj];
                    mma_bf16(acc, aH, &bH[jj * 2]);
                    mma_bf16(acc, aH, &bL[jj * 2]);
                    mma_bf16(acc, aL, &bH[jj * 2]);
                }
            }
        }

        const bool need_mask = (j0 + 63 > qrow0);
        #pragma unroll
        for (int j = 0; j < 8; j++) {
            int colb = j0 + j * 8 + tig * 2;
            #pragma unroll
            for (int e = 0; e < 4; e++) {
                float v = s[j][e] * 0.125f;
                if (need_mask) {
                    int col = colb + (e & 1);
                    int row = (e < 2) ? qrow0 : qrow1;
                    if (col > row) v = -1e30f;
                }
                s[j][e] = v;
            }
        }

        float mx0 = -1e30f, mx1 = -1e30f;
        #pragma unroll
        for (int j = 0; j < 8; j++) {
            mx0 = fmaxf(mx0, fmaxf(s[j][0], s[j][1]));
            mx1 = fmaxf(mx1, fmaxf(s[j][2], s[j][3]));
        }
        mx0 = fmaxf(mx0, __shfl_xor_sync(0xffffffffu, mx0, 1));
        mx0 = fmaxf(mx0, __shfl_xor_sync(0xffffffffu, mx0, 2));
        mx1 = fmaxf(mx1, __shfl_xor_sync(0xffffffffu, mx1, 1));
        mx1 = fmaxf(mx1, __shfl_xor_sync(0xffffffffu, mx1, 2));
        float mn0 = fmaxf(m0, mx0), mn1 = fmaxf(m1, mx1);
        float f0 = __expf(m0 - mn0), f1 = __expf(m1 - mn1);
        m0 = mn0; m1 = mn1;

        float sum0 = 0.f, sum1 = 0.f;
        #pragma unroll
        for (int j = 0; j < 8; j++) {
            s[j][0] = __expf(s[j][0] - mn0);
            s[j][1] = __expf(s[j][1] - mn0);
            s[j][2] = __expf(s[j][2] - mn1);
            s[j][3] = __expf(s[j][3] - mn1);
            sum0 += s[j][0] + s[j][1];
            sum1 += s[j][2] + s[j][3];
        }
        sum0 += __shfl_xor_sync(0xffffffffu, sum0, 1);
        sum0 += __shfl_xor_sync(0xffffffffu, sum0, 2);
        sum1 += __shfl_xor_sync(0xffffffffu, sum1, 1);
        sum1 += __shfl_xor_sync(0xffffffffu, sum1, 2);
        l0 = l0 * f0 + sum0;
        l1 = l1 * f1 + sum1;

        #pragma unroll
        for (int j = 0; j < 8; j++) {
            O[j][0] *= f0; O[j][1] *= f0;
            O[j][2] *= f1; O[j][3] *= f1;
        }

        #pragma unroll
        for (int ks2 = 0; ks2 < 4; ks2++) {
            uint32_t aPh[4], aPl[4];
            const float* p0 = s[ks2 * 2];
            const float* p1 = s[ks2 * 2 + 1];
            split2(p0[0], p0[1], aPh[0], aPl[0]);
            split2(p0[2], p0[3], aPh[1], aPl[1]);
            split2(p1[0], p1[1], aPh[2], aPl[2]);
            split2(p1[2], p1[3], aPh[3], aPl[3]);
            #pragma unroll
            for (int nf = 0; nf < 4; nf++) {
                uint32_t vH[4], vL[4];
                uint32_t voff = (uint32_t)((ks2 * 16 + v_r) * FP + nf * 16 + v_n) * 2;
                ldsm4t(vH, sb + SVH + voff);
                ldsm4t(vL, sb + SVL + voff);
                #pragma unroll
                for (int jj = 0; jj < 2; jj++) {
                    float* acc = O[nf * 2 + jj];
                    mma_bf16(acc, aPh, &vH[jj * 2]);
                    mma_bf16(acc, aPh, &vL[jj * 2]);
                    mma_bf16(acc, aPl, &vH[jj * 2]);
                }
            }
        }
    }

    const float inv0 = 1.f / l0, inv1 = 1.f / l1;
    #pragma unroll
    for (int j = 0; j < 8; j++) {
        int col = h * HD + j * 8 + tig * 2;
        size_t o0 = (size_t)(b * TT + qrow0) * CC + col;
        size_t o1 = o0 + 8 * CC;
        uint32_t hv, lv;
        split2(O[j][0] * inv0, O[j][1] * inv0, hv, lv);
        *(uint32_t*)&g_yhi[o0] = hv;
        *(uint32_t*)&g_ylo[o0] = lv;
        split2(O[j][2] * inv1, O[j][3] * inv1, hv, lv);
        *(uint32_t*)&g_yhi[o1] = hv;
        *(uint32_t*)&g_ylo[o1] = lv;
    }
}

// ---------------------------------------------------------------------------
extern "C" void kernel_launch(void* const* d_in, const int* in_sizes, int n_in,
                              void* d_out, int out_size)
{
    const float* x     = (const float*)d_in[0];
    const float* w_qkv = (const float*)d_in[1];
    const float* b_qkv = (const float*)d_in[2];
    const float* w_out = (const float*)d_in[3];
    const float* b_out = (const float*)d_in[4];
    float* out = (float*)d_out;

    float* qkv; cudaGetSymbolAddress((void**)&qkv, g_qkv);
    __nv_bfloat16 *xhi, *xlo, *yhi, *ylo, *wqh, *wql, *woh, *wol;
    cudaGetSymbolAddress((void**)&xhi, g_xhi);
    cudaGetSymbolAddress((void**)&xlo, g_xlo);
    cudaGetSymbolAddress((void**)&yhi, g_yhi);
    cudaGetSymbolAddress((void**)&ylo, g_ylo);
    cudaGetSymbolAddress((void**)&wqh, g_wqkvT_hi);
    cudaGetSymbolAddress((void**)&wql, g_wqkvT_lo);
    cudaGetSymbolAddress((void**)&woh, g_woutT_hi);
    cudaGetSymbolAddress((void**)&wol, g_woutT_lo);

    cudaFuncSetAttribute(mma_gemm_bias_kernel,
                         cudaFuncAttributeMaxDynamicSharedMemorySize, GEMM_SMEM_DYN);
    cudaFuncSetAttribute(flash_attn_mma_kernel,
                         cudaFuncAttributeMaxDynamicSharedMemorySize, FA_SMEM);

    // 1) split x -> bf16 hi/lo
    split_kernel<<<(MM * CC / 4 + 255) / 256, 256>>>(x, xhi, xlo, MM * CC);
    // 2) transpose+split weights
    {
        dim3 g1(3 * CC / 32, CC / 32);
        transpose_split_kernel<<<g1, 256>>>(w_qkv, wqh, wql, CC, 3 * CC);
        dim3 g2(CC / 32, CC / 32);
        transpose_split_kernel<<<g2, 256>>>(w_out, woh, wol, CC, CC);
    }
    // 3) qkv = x @ w_qkv + b_qkv   [4096, 3072]
    {
        dim3 grid(3 * CC / 128, MM / 128);
        mma_gemm_bias_kernel<<<grid, 256, GEMM_SMEM_DYN>>>(
            xhi, xlo, wqh, wql, b_qkv, qkv, MM, 3 * CC, CC);
    }
    // 4) flash attention (mma.sync) -> g_yhi/g_ylo directly
    {
        dim3 grid(TT / 128, HH, BB);
        flash_attn_mma_kernel<<<grid, 256, FA_SMEM>>>();
    }
    // 5) out = y @ w_out + b_out   [4096, 1024]
    {
        dim3 grid(CC / 128, MM / 128);
        mma_gemm_bias_kernel<<<grid, 256, GEMM_SMEM_DYN>>>(
            yhi, ylo, woh, wol, b_out, out, MM, CC, CC);
    }
}